// round 1
// baseline (speedup 1.0000x reference)
#include <cuda_runtime.h>
#include <cstdint>
#include <cstddef>

#define BB 512
#define TJ 32
#define TK 128
#define TI 128
#define NT 256

// Face accumulators: {exp-sum, masked-x-sum}
__device__ float2 gF0[BB * BB];  // [j*B+k]: E0 = sum_i exp, S0 = sum_{i:b_i==b_j} x
__device__ float2 gF1[BB * BB];  // [i*B+k]: E1 = sum_j exp, S1 = sum_{j:b_j==b_i} x
__device__ float2 gF2[BB * BB];  // [i*B+j]: E2 = sum_k exp, S2 = sum_{k:b_k==b_i} x
__device__ int gCls[BB];
__device__ int gCnt1;

__device__ __forceinline__ void redAdd2(float2* p, float a, float b) {
    asm volatile("red.global.add.v2.f32 [%0], {%1, %2};"
                 :: "l"(p), "f"(a), "f"(b) : "memory");
}

__global__ void zero_kernel(float* out) {
    int t = blockIdx.x * blockDim.x + threadIdx.x;  // exactly B*B threads
    float2 z = make_float2(0.f, 0.f);
    gF0[t] = z; gF1[t] = z; gF2[t] = z;
    if (t == 0) { gCnt1 = 0; out[0] = 0.f; }
}

__global__ void class_kernel(const float* __restrict__ target) {
    int i = threadIdx.x;  // 512 threads, 1 block
    // round(t) >= 0  <=>  t >= -0.5 (round-half-even: round(-0.5) = -0 >= 0)
    int b = (target[i] >= -0.5f) ? 1 : 0;
    gCls[i] = b;
    unsigned m = __ballot_sync(0xffffffffu, b);
    if ((i & 31) == 0) atomicAdd(&gCnt1, __popc(m));
}

__global__ __launch_bounds__(NT) void main_kernel(const float* __restrict__ x) {
    const int j0 = blockIdx.x * TJ;   // 16 tiles
    const int k0 = blockIdx.y * TK;   // 4 tiles
    const int i0 = blockIdx.z * TI;   // 4 splits
    const int tid  = threadIdx.x;
    const int lane = tid & 31;
    const int w    = tid >> 5;        // warp 0..7
    const int kk   = k0 + lane * 4;   // this thread's 4 consecutive k
    const int jrow = j0 + w * 4;      // this warp's 4 consecutive j rows

    __shared__ int scls[BB];
    __shared__ __align__(16) float2 sP[2][8][TK];  // 16 KB staging for E1/S1

    for (int t = tid; t < BB; t += NT) scls[t] = gCls[t];
    __syncthreads();

    int ck[4], cj[4];
#pragma unroll
    for (int q = 0; q < 4; q++) ck[q] = scls[kk + q];
#pragma unroll
    for (int r = 0; r < 4; r++) cj[r] = scls[jrow + r];

    float2 a0[16];  // E0/S0 accumulators per (row r, k q)
#pragma unroll
    for (int t = 0; t < 16; t++) a0[t] = make_float2(0.f, 0.f);

    for (int ii = 0; ii < TI; ii++) {
        const int i = i0 + ii;
        const int ci = scls[i];
        const int buf = ii & 1;
        float mik[4];
#pragma unroll
        for (int q = 0; q < 4; q++) mik[q] = (ck[q] == ci) ? 1.f : 0.f;

        const float4* p = reinterpret_cast<const float4*>(
            x + ((size_t)i << 18) + ((size_t)jrow << 9) + (size_t)kk);

        float2 P[4];  // per-k {exp, fij*x} summed over this thread's 4 rows
#pragma unroll
        for (int q = 0; q < 4; q++) P[q] = make_float2(0.f, 0.f);

#pragma unroll
        for (int r = 0; r < 4; r++) {
            float4 v = p[(size_t)r * (BB / 4)];
            float fij = (cj[r] == ci) ? 1.f : 0.f;
            float e0 = __expf(v.x), e1 = __expf(v.y);
            float e2 = __expf(v.z), e3 = __expf(v.w);
            float s0 = fij * v.x, s1 = fij * v.y;
            float s2 = fij * v.z, s3 = fij * v.w;

            // E0/S0 (register-local over i)
            a0[r*4+0].x += e0; a0[r*4+0].y += s0;
            a0[r*4+1].x += e1; a0[r*4+1].y += s1;
            a0[r*4+2].x += e2; a0[r*4+2].y += s2;
            a0[r*4+3].x += e3; a0[r*4+3].y += s3;
            // E1/S1 partial (summed over rows, per k)
            P[0].x += e0; P[0].y += s0;
            P[1].x += e1; P[1].y += s1;
            P[2].x += e2; P[2].y += s2;
            P[3].x += e3; P[3].y += s3;

            // E2/S2: reduce this row over the warp's 128 k
            float re = (e0 + e1) + (e2 + e3);
            float rs = mik[0] * v.x + mik[1] * v.y + mik[2] * v.z + mik[3] * v.w;
#pragma unroll
            for (int o = 16; o > 0; o >>= 1) {
                re += __shfl_xor_sync(0xffffffffu, re, o);
                rs += __shfl_xor_sync(0xffffffffu, rs, o);
            }
            if (lane == 0)
                redAdd2(&gF2[(size_t)i * BB + jrow + r], re, rs);
        }

        // stage E1/S1 partials
        float4* d = reinterpret_cast<float4*>(&sP[buf][w][lane * 4]);
        d[0] = make_float4(P[0].x, P[0].y, P[1].x, P[1].y);
        d[1] = make_float4(P[2].x, P[2].y, P[3].x, P[3].y);
        __syncthreads();

        if (tid < TK) {
            float2 s = sP[buf][0][tid];
#pragma unroll
            for (int ww = 1; ww < 8; ww++) {
                float2 t2 = sP[buf][ww][tid];
                s.x += t2.x; s.y += t2.y;
            }
            redAdd2(&gF1[(size_t)i * BB + k0 + tid], s.x, s.y);
        }
    }

    // flush E0/S0 (4 i-split contributors per address)
#pragma unroll
    for (int r = 0; r < 4; r++)
#pragma unroll
        for (int q = 0; q < 4; q++)
            redAdd2(&gF0[(size_t)(jrow + r) * BB + kk + q],
                    a0[r*4+q].x, a0[r*4+q].y);
}

__global__ void finalize_kernel(float* __restrict__ out) {
    int t = blockIdx.x * blockDim.x + threadIdx.x;  // B*B threads
    int a = t >> 9, b = t & (BB - 1);
    float c = 0.f;
    int ca = gCls[a];
    if (ca == gCls[b]) {
        int n1 = gCnt1;
        float n = (float)((ca == 1) ? n1 : (BB - n1));
        float inv = 1.0f / n;
        float2 f0 = gF0[t], f1 = gF1[t], f2 = gF2[t];
        c = __logf(f0.x) + __logf(f1.x) + __logf(f2.x)
            - (f0.y + f1.y + f2.y) * inv;
    }
    c *= (1.0f / (float)(BB * BB));
#pragma unroll
    for (int o = 16; o > 0; o >>= 1) c += __shfl_xor_sync(0xffffffffu, c, o);
    __shared__ float sacc[16];
    if ((threadIdx.x & 31) == 0) sacc[threadIdx.x >> 5] = c;
    __syncthreads();
    if (threadIdx.x < 16) {
        float v = sacc[threadIdx.x];
#pragma unroll
        for (int o = 8; o > 0; o >>= 1) v += __shfl_xor_sync(0xffffu, v, o);
        if (threadIdx.x == 0) atomicAdd(out, v);
    }
}

extern "C" void kernel_launch(void* const* d_in, const int* in_sizes, int n_in,
                              void* d_out, int out_size) {
    const float* cube   = (const float*)d_in[0];
    const float* target = (const float*)d_in[1];
    if (n_in >= 2 && in_sizes[0] < in_sizes[1]) {  // defensive order check
        cube   = (const float*)d_in[1];
        target = (const float*)d_in[0];
    }
    float* out = (float*)d_out;

    zero_kernel<<<BB * BB / 512, 512>>>(out);
    class_kernel<<<1, BB>>>(target);
    dim3 grid(BB / TJ, BB / TK, BB / TI);  // (16, 4, 4)
    main_kernel<<<grid, NT>>>(cube);
    finalize_kernel<<<BB * BB / 512, 512>>>(out);
}

// round 4
// speedup vs baseline: 1.6822x; 1.6822x over previous
#include <cuda_runtime.h>
#include <cstdint>
#include <cstddef>

#define BB 512
#define NT 512
#define NW 16    // warps per block
#define RPW 2    // j-rows per warp
#define TK 128   // k per tile (lane*4)
#define TJ 32    // j per tile (NW*RPW)
#define TI 16    // i per tile
#define NJT 16   // BB/TJ
#define NKT 4    // BB/TK
#define NIT 32   // BB/TI
#define NTILE (NJT * NKT * NIT)  // 2048
#define GRID 296                 // 2 * 148 SMs

// Face accumulators: {exp-sum, masked-x-sum}
__device__ float2 gF0[BB * BB];  // [j*B+k]: sum over i
__device__ float2 gF1[BB * BB];  // [i*B+k]: sum over j
__device__ float2 gF2[BB * BB];  // [i*B+j]: sum over k
__device__ int gCls[BB];
__device__ int gCnt1;

__device__ __forceinline__ void redAdd2(float2* p, float a, float b) {
    asm volatile("red.global.add.v2.f32 [%0], {%1, %2};"
                 :: "l"(p), "f"(a), "f"(b));
}

__global__ void zero_kernel(float* out) {
    int t = blockIdx.x * blockDim.x + threadIdx.x;  // exactly B*B threads
    float2 z = make_float2(0.f, 0.f);
    gF0[t] = z; gF1[t] = z; gF2[t] = z;
    if (t == 0) { gCnt1 = 0; out[0] = 0.f; }
}

__global__ void class_kernel(const float* __restrict__ target) {
    int i = threadIdx.x;  // 512 threads, 1 block
    // round(t) >= 0  <=>  t >= -0.5 (round-half-even: round(-0.5) = -0 >= 0)
    int b = (target[i] >= -0.5f) ? 1 : 0;
    gCls[i] = b;
    unsigned m = __ballot_sync(0xffffffffu, b);
    if ((i & 31) == 0) atomicAdd(&gCnt1, __popc(m));
}

// element offset of a tile's first element for this (warp, lane)
__device__ __forceinline__ size_t tile_off(int t, int w, int lane) {
    int it = t >> 6;          // i-split index (0..31)
    int rem = t & 63;
    int jt = rem >> 2;        // j tile (0..15)
    int kt = rem & 3;         // k tile (0..3)
    return ((size_t)(it * TI) << 18)
         + ((size_t)(jt * TJ + w * RPW) << 9)
         + (size_t)(kt * TK + lane * 4);
}

__global__ __launch_bounds__(NT, 2) void main_kernel(const float* __restrict__ x) {
    const int tid  = threadIdx.x;
    const int lane = tid & 31;
    const int w    = tid >> 5;  // 0..15
    const unsigned FULL = 0xffffffffu;

    __shared__ int scls[BB];
    __shared__ __align__(16) float2 sP[2][NW][TK];  // 32 KB F1 staging

    for (int t = tid; t < BB; t += NT) scls[t] = gCls[t];
    __syncthreads();

    for (int t = blockIdx.x; t < NTILE; t += GRID) {
        const int it = t >> 6;
        const int rem = t & 63;
        const int j0 = (rem >> 2) * TJ;
        const int k0 = (rem & 3) * TK;
        const int i0 = it * TI;
        const int kk = k0 + lane * 4;
        const int jrow = j0 + w * RPW;

        const int ck0 = scls[kk],   ck1 = scls[kk + 1];
        const int ck2 = scls[kk + 2], ck3 = scls[kk + 3];
        const int cj0 = scls[jrow], cj1 = scls[jrow + 1];

        float2 a0[8];  // F0 accumulators: 2 rows x 4 k
#pragma unroll
        for (int q = 0; q < 8; q++) a0[q] = make_float2(0.f, 0.f);

        const float* p = x + tile_off(t, w, lane);
        float4 v0 = *reinterpret_cast<const float4*>(p);
        float4 v1 = *reinterpret_cast<const float4*>(p + BB);

        for (int ii = 0; ii < TI; ii++) {
            const int i = i0 + ii;
            const int ci = scls[i];
            const int buf = ii & 1;

            // prefetch next row pair (next i, or next tile's start)
            const float* pn;
            if (ii + 1 < TI) pn = p + (1 << 18);
            else {
                int tn = t + GRID;
                pn = (tn < NTILE) ? (x + tile_off(tn, w, lane)) : p;
            }
            float4 n0 = *reinterpret_cast<const float4*>(pn);
            float4 n1 = *reinterpret_cast<const float4*>(pn + BB);

            const float m0 = (ck0 == ci) ? 1.f : 0.f;
            const float m1 = (ck1 == ci) ? 1.f : 0.f;
            const float m2 = (ck2 == ci) ? 1.f : 0.f;
            const float m3 = (ck3 == ci) ? 1.f : 0.f;
            const float fij0 = (cj0 == ci) ? 1.f : 0.f;
            const float fij1 = (cj1 == ci) ? 1.f : 0.f;

            float2 P0 = make_float2(0.f, 0.f), P1 = P0, P2 = P0, P3 = P0;
            float re0, rs0, re1, rs1;

            {   // row 0
                float e0 = __expf(v0.x), e1 = __expf(v0.y), e2 = __expf(v0.z), e3 = __expf(v0.w);
                float s0 = fij0 * v0.x, s1 = fij0 * v0.y, s2 = fij0 * v0.z, s3 = fij0 * v0.w;
                a0[0].x += e0; a0[0].y += s0;  P0.x += e0; P0.y += s0;
                a0[1].x += e1; a0[1].y += s1;  P1.x += e1; P1.y += s1;
                a0[2].x += e2; a0[2].y += s2;  P2.x += e2; P2.y += s2;
                a0[3].x += e3; a0[3].y += s3;  P3.x += e3; P3.y += s3;
                re0 = (e0 + e1) + (e2 + e3);
                rs0 = m0 * v0.x + m1 * v0.y + m2 * v0.z + m3 * v0.w;
            }
            {   // row 1
                float e0 = __expf(v1.x), e1 = __expf(v1.y), e2 = __expf(v1.z), e3 = __expf(v1.w);
                float s0 = fij1 * v1.x, s1 = fij1 * v1.y, s2 = fij1 * v1.z, s3 = fij1 * v1.w;
                a0[4].x += e0; a0[4].y += s0;  P0.x += e0; P0.y += s0;
                a0[5].x += e1; a0[5].y += s1;  P1.x += e1; P1.y += s1;
                a0[6].x += e2; a0[6].y += s2;  P2.x += e2; P2.y += s2;
                a0[7].x += e3; a0[7].y += s3;  P3.x += e3; P3.y += s3;
                re1 = (e0 + e1) + (e2 + e3);
                rs1 = m0 * v1.x + m1 * v1.y + m2 * v1.z + m3 * v1.w;
            }

            // F2: value-packed butterfly. 6 SHFL reduce 4 scalars x 32 lanes.
            {
                bool hi16 = (lane & 16) != 0;
                float kE = hi16 ? re1 : re0, sE = hi16 ? re0 : re1;
                float kS = hi16 ? rs1 : rs0, sS = hi16 ? rs0 : rs1;
                kE += __shfl_xor_sync(FULL, sE, 16);
                kS += __shfl_xor_sync(FULL, sS, 16);
                bool hi8 = (lane & 8) != 0;
                float kv = hi8 ? kS : kE, sv = hi8 ? kE : kS;
                kv += __shfl_xor_sync(FULL, sv, 8);
                kv += __shfl_xor_sync(FULL, kv, 4);
                kv += __shfl_xor_sync(FULL, kv, 2);
                kv += __shfl_xor_sync(FULL, kv, 1);
                // lanes 0:E(row0) 8:S(row0) 16:E(row1) 24:S(row1)
                if ((lane & 7) == 0) {
                    float* fb = reinterpret_cast<float*>(&gF2[(size_t)i * BB + jrow]);
                    atomicAdd(fb + (lane >> 3), kv);  // 4-lane RED, consecutive floats
                }
            }

            // F1: stage per-k partials, then balanced gather (all 512 threads)
            float4* d = reinterpret_cast<float4*>(&sP[buf][w][lane * 4]);
            d[0] = make_float4(P0.x, P0.y, P1.x, P1.y);
            d[1] = make_float4(P2.x, P2.y, P3.x, P3.y);
            __syncthreads();
            {
                int kx = tid & (TK - 1);
                int g = tid >> 7;  // 0..3 -> warps g*4..g*4+3
                float2 s = sP[buf][g * 4 + 0][kx];
                float2 t1 = sP[buf][g * 4 + 1][kx];
                float2 t2 = sP[buf][g * 4 + 2][kx];
                float2 t3 = sP[buf][g * 4 + 3][kx];
                s.x += t1.x + t2.x + t3.x;
                s.y += t1.y + t2.y + t3.y;
                redAdd2(&gF1[(size_t)i * BB + k0 + kx], s.x, s.y);
            }

            v0 = n0; v1 = n1; p = pn;
        }

        // flush F0 for this tile
#pragma unroll
        for (int r = 0; r < RPW; r++)
#pragma unroll
            for (int q = 0; q < 4; q++)
                redAdd2(&gF0[(size_t)(jrow + r) * BB + kk + q],
                        a0[r * 4 + q].x, a0[r * 4 + q].y);
    }
}

__global__ void finalize_kernel(float* __restrict__ out) {
    int t = blockIdx.x * blockDim.x + threadIdx.x;  // B*B threads
    int a = t >> 9, b = t & (BB - 1);
    float c = 0.f;
    int ca = gCls[a];
    if (ca == gCls[b]) {
        int n1 = gCnt1;
        float n = (float)((ca == 1) ? n1 : (BB - n1));
        float inv = 1.0f / n;
        float2 f0 = gF0[t], f1 = gF1[t], f2 = gF2[t];
        c = __logf(f0.x) + __logf(f1.x) + __logf(f2.x)
            - (f0.y + f1.y + f2.y) * inv;
    }
    c *= (1.0f / (float)(BB * BB));
#pragma unroll
    for (int o = 16; o > 0; o >>= 1) c += __shfl_xor_sync(0xffffffffu, c, o);
    __shared__ float sacc[16];
    if ((threadIdx.x & 31) == 0) sacc[threadIdx.x >> 5] = c;
    __syncthreads();
    if (threadIdx.x < 16) {
        float v = sacc[threadIdx.x];
#pragma unroll
        for (int o = 8; o > 0; o >>= 1) v += __shfl_xor_sync(0xffffu, v, o);
        if (threadIdx.x == 0) atomicAdd(out, v);
    }
}

extern "C" void kernel_launch(void* const* d_in, const int* in_sizes, int n_in,
                              void* d_out, int out_size) {
    const float* cube   = (const float*)d_in[0];
    const float* target = (const float*)d_in[1];
    if (n_in >= 2 && in_sizes[0] < in_sizes[1]) {  // defensive order check
        cube   = (const float*)d_in[1];
        target = (const float*)d_in[0];
    }
    float* out = (float*)d_out;

    zero_kernel<<<BB * BB / 512, 512>>>(out);
    class_kernel<<<1, BB>>>(target);
    main_kernel<<<GRID, NT>>>(cube);
    finalize_kernel<<<BB * BB / 512, 512>>>(out);
}